// round 4
// baseline (speedup 1.0000x reference)
#include <cuda_runtime.h>
#include <math.h>
#include <stdint.h>

#define Bb 8
#define Tt 24
#define NN 263
#define Dd 512

// ---------------- scratch (static device globals; no allocation) ----------------
__device__ float g_P[71098368];      // 50496 x 1408  x-projections
__device__ float g_P0[2359296];      // 6144 x 384    agg0 projections
__device__ float g_P1[4718592];      // 12288 x 384   agg1 projections
__device__ float g_Wcat[720896];     // 1408 x 512
__device__ float g_Wcat0[196608];    // 384 x 512
__device__ float g_Wcat1[196608];    // 384 x 512
__device__ float g_sx0[786432];      // B*T*2*32*64
__device__ float g_sx1[1572864];     // B*T*2*64*64
__device__ float g_sg[6463488];      // 50496 x 128
__device__ float g_tgx[3231744];     // 8*263*12*128
__device__ float g_st[32317440];     // 50496 x 640
__device__ float g_lam;

// ---------------- helpers ----------------
__device__ __forceinline__ float warpMax(float v){
    #pragma unroll
    for (int o=16;o;o>>=1) v = fmaxf(v, __shfl_xor_sync(0xffffffffu, v, o));
    return v;
}
__device__ __forceinline__ float warpSum(float v){
    #pragma unroll
    for (int o=16;o;o>>=1) v += __shfl_xor_sync(0xffffffffu, v, o);
    return v;
}
__device__ __forceinline__ void tf32_split(float v, uint32_t& hi, uint32_t& lo){
    uint32_t h; asm("cvt.rna.tf32.f32 %0, %1;" : "=r"(h) : "f"(v));
    float l = v - __uint_as_float(h);
    uint32_t lw; asm("cvt.rna.tf32.f32 %0, %1;" : "=r"(lw) : "f"(l));
    hi = h; lo = lw;
}

#define MMA_TF32(c, a, b) \
    asm volatile("mma.sync.aligned.m16n8k8.row.col.f32.tf32.tf32.f32 " \
        "{%0,%1,%2,%3},{%4,%5,%6,%7},{%8,%9},{%0,%1,%2,%3};" \
        : "+f"((c)[0]),"+f"((c)[1]),"+f"((c)[2]),"+f"((c)[3]) \
        : "r"((a)[0]),"r"((a)[1]),"r"((a)[2]),"r"((a)[3]),"r"((b)[0]),"r"((b)[1]))

// ---------------- lam scalar ----------------
__global__ void lam_kernel(const float* __restrict__ lq1, const float* __restrict__ lk1,
                           const float* __restrict__ lq2, const float* __restrict__ lk2)
{
    int l = threadIdx.x;
    float a = lq1[l]*lk1[l];
    float b = lq2[l]*lk2[l];
    a = warpSum(a); b = warpSum(b);
    if (l == 0) g_lam = expf(a) - expf(b) + 0.2f;   // LAMBDA_INIT = 0.2
}

// ---------------- tf32 tensor-core NT GEMM with 3xTF32 compensation ----------------
// C[m, coff+n] = sum_k A[m,k]*B[n,k] (+bias[n])
// Tile: BM=64, BN=128, BK=16. Requires M%64==0, N%128==0, K%16==0.
__global__ __launch_bounds__(256)
void gemm_tf32(const float* __restrict__ A, const float* __restrict__ B,
               float* __restrict__ C, const float* __restrict__ bias,
               int M, int N, int K, int ldc, int coff)
{
    __shared__ uint32_t Ah[16][72], Al[16][72];      // stride 72 (== 8 mod 32)
    __shared__ uint32_t Bh[16][136], Bl[16][136];    // stride 136 (== 8 mod 32)
    const int tid  = threadIdx.x;
    const int bm   = blockIdx.y * 64, bn = blockIdx.x * 128;
    const int warp = tid >> 5, lane = tid & 31;
    const int wm   = warp & 1, wn = warp >> 1;       // 2x4 warps, 32x32 each
    const int g    = lane >> 2, tg = lane & 3;

    // load mappings (chosen for conflict-free smem stores)
    const int ar  = tid & 63,  ac  = tid >> 6;   // A: 1 float4
    const int br  = tid & 127, bcc = tid >> 7;   // B: 2 float4 (k chunks bcc*4 and bcc*4+8)

    float acc[2][4][4];
    #pragma unroll
    for (int i=0;i<2;i++)
        #pragma unroll
        for (int j=0;j<4;j++)
            #pragma unroll
            for (int q=0;q<4;q++) acc[i][j][q] = 0.f;

    const float* Ag  = A + (size_t)(bm + ar) * K + ac*4;
    const float* Bg0 = B + (size_t)(bn + br) * K + bcc*4;
    const float* Bg1 = Bg0 + 8;

    float4 av  = *(const float4*)Ag;
    float4 bv0 = *(const float4*)Bg0;
    float4 bv1 = *(const float4*)Bg1;

    for (int k0 = 0; k0 < K; k0 += 16) {
        __syncthreads();
        {   // split + store A
            float va[4] = {av.x, av.y, av.z, av.w};
            #pragma unroll
            for (int j=0;j<4;j++){
                uint32_t h,l2; tf32_split(va[j], h, l2);
                Ah[ac*4+j][ar] = h; Al[ac*4+j][ar] = l2;
            }
            float vb0[4] = {bv0.x, bv0.y, bv0.z, bv0.w};
            float vb1[4] = {bv1.x, bv1.y, bv1.z, bv1.w};
            #pragma unroll
            for (int j=0;j<4;j++){
                uint32_t h,l2; tf32_split(vb0[j], h, l2);
                Bh[bcc*4+j][br] = h; Bl[bcc*4+j][br] = l2;
                tf32_split(vb1[j], h, l2);
                Bh[bcc*4+8+j][br] = h; Bl[bcc*4+8+j][br] = l2;
            }
        }
        __syncthreads();
        if (k0 + 16 < K) {   // prefetch next tile (overlaps MMA)
            av  = *(const float4*)(Ag  + k0 + 16);
            bv0 = *(const float4*)(Bg0 + k0 + 16);
            bv1 = *(const float4*)(Bg1 + k0 + 16);
        }
        #pragma unroll
        for (int ks = 0; ks < 16; ks += 8) {
            uint32_t afh[2][4], afl[2][4], bfh[4][2], bfl[4][2];
            #pragma unroll
            for (int mi=0; mi<2; mi++){
                int mr = wm*32 + mi*16;
                afh[mi][0] = Ah[ks+tg  ][mr+g  ];
                afh[mi][1] = Ah[ks+tg  ][mr+g+8];
                afh[mi][2] = Ah[ks+tg+4][mr+g  ];
                afh[mi][3] = Ah[ks+tg+4][mr+g+8];
                afl[mi][0] = Al[ks+tg  ][mr+g  ];
                afl[mi][1] = Al[ks+tg  ][mr+g+8];
                afl[mi][2] = Al[ks+tg+4][mr+g  ];
                afl[mi][3] = Al[ks+tg+4][mr+g+8];
            }
            #pragma unroll
            for (int ni=0; ni<4; ni++){
                int nc = wn*32 + ni*8;
                bfh[ni][0] = Bh[ks+tg  ][nc+g];
                bfh[ni][1] = Bh[ks+tg+4][nc+g];
                bfl[ni][0] = Bl[ks+tg  ][nc+g];
                bfl[ni][1] = Bl[ks+tg+4][nc+g];
            }
            #pragma unroll
            for (int mi=0; mi<2; mi++)
                #pragma unroll
                for (int ni=0; ni<4; ni++){
                    MMA_TF32(acc[mi][ni], afh[mi], bfh[ni]);
                    MMA_TF32(acc[mi][ni], afl[mi], bfh[ni]);
                    MMA_TF32(acc[mi][ni], afh[mi], bfl[ni]);
                }
        }
    }

    #pragma unroll
    for (int mi=0; mi<2; mi++){
        #pragma unroll
        for (int ni=0; ni<4; ni++){
            int gr = bm + wm*32 + mi*16 + g;
            int gc = bn + wn*32 + ni*8 + 2*tg;
            float b0 = bias ? bias[gc]   : 0.f;
            float b1 = bias ? bias[gc+1] : 0.f;
            float* Cp = C + (size_t)gr*ldc + coff + gc;
            Cp[0] = acc[mi][ni][0] + b0;
            Cp[1] = acc[mi][ni][1] + b1;
            Cp += (size_t)8*ldc;
            Cp[0] = acc[mi][ni][2] + b0;
            Cp[1] = acc[mi][ni][3] + b1;
        }
    }
}

// ---------------- spatial diff-attention (branch 1) ----------------
// grid (H=4, T, B), block 256 (8 warps, 2 queries per warp pass).
// P cols: q_s 0..255, k_s 256..511, v_s 512..767
// Combined prob: pc = p1/sum1 - lam*p2/sum2, so AV is a single pass.
__global__ __launch_bounds__(256)
void spatial_kernel(const float* __restrict__ P, float* __restrict__ st,
                    const float* __restrict__ ln_g, const float* __restrict__ ln_b)
{
    extern __shared__ float sm[];
    float* k1s = sm;                    // 263 x 36 (padded, conflict-free float4)
    float* k2s = k1s + NN*36;           // 263 x 36
    float* vs  = k2s + NN*36;           // 263 x 64
    float* pc  = vs  + NN*64;           // 16 slots x 264 (8 warps x 2 queries)
    float* qs  = pc  + 16*264;          // 8 x 64
    const int h = blockIdx.x, t = blockIdx.y, b = blockIdx.z;
    const size_t r0 = ((size_t)b*Tt + t) * NN;
    const int tid = threadIdx.x;

    for (int i = tid; i < NN*32; i += 256) {
        int m = i >> 5, d = i & 31;
        const float* row = P + (r0 + m) * 1408 + h*64;
        k1s[m*36+d] = row[256 + d];
        k2s[m*36+d] = row[288 + d];
    }
    for (int i = tid; i < NN*64; i += 256) {
        int m = i >> 6, e = i & 63;
        vs[i] = P[(r0+m)*1408 + 512 + h*64 + e];
    }
    __syncthreads();

    const float lam = g_lam;
    const int w = tid >> 5, l = tid & 31;
    float* qw  = qs + w*64;
    const float gl0 = ln_g[l], gl1 = ln_g[32+l];
    const float bl0 = ln_b[l], bl1 = ln_b[32+l];
    const float sc = 0.17677669529663687f;  // 32^-0.5

    for (int nb = 2*w; nb < 272; nb += 16) {
        // ---- score + softmax + combined-prob for two queries ----
        #pragma unroll
        for (int qi = 0; qi < 2; qi++) {
            int n = nb + qi;
            int nclamp = n < NN ? n : NN-1;
            const float* qrow = P + (r0+nclamp)*1408 + h*64;
            qw[l] = qrow[l]; qw[32+l] = qrow[32+l];
            __syncwarp();
            float sc1[9], sc2[9];
            #pragma unroll
            for (int mi=0; mi<9; mi++){ sc1[mi]=0.f; sc2[mi]=0.f; }
            #pragma unroll
            for (int dd=0; dd<8; dd++){
                float4 qa = *(const float4*)&qw[dd*4];
                float4 qb = *(const float4*)&qw[32+dd*4];
                #pragma unroll
                for (int mi=0; mi<9; mi++){
                    int m = l + (mi<<5);
                    int mc = m < NN ? m : 0;
                    float4 kA = *(const float4*)&k1s[mc*36 + dd*4];
                    float4 kB = *(const float4*)&k2s[mc*36 + dd*4];
                    sc1[mi] += qa.x*kA.x + qa.y*kA.y + qa.z*kA.z + qa.w*kA.w;
                    sc2[mi] += qb.x*kB.x + qb.y*kB.y + qb.z*kB.z + qb.w*kB.w;
                }
            }
            float mx1 = -1e30f, mx2 = -1e30f;
            #pragma unroll
            for (int mi=0; mi<9; mi++){
                int m = l + (mi<<5);
                if (m < NN){
                    sc1[mi] *= sc; sc2[mi] *= sc;
                    mx1 = fmaxf(mx1, sc1[mi]); mx2 = fmaxf(mx2, sc2[mi]);
                } else { sc1[mi] = -1e30f; sc2[mi] = -1e30f; }
            }
            mx1 = warpMax(mx1); mx2 = warpMax(mx2);
            float sum1 = 0.f, sum2 = 0.f;
            #pragma unroll
            for (int mi=0; mi<9; mi++){
                int m = l + (mi<<5);
                if (m < NN){
                    sc1[mi] = __expf(sc1[mi]-mx1);
                    sc2[mi] = __expf(sc2[mi]-mx2);
                    sum1 += sc1[mi]; sum2 += sc2[mi];
                }
            }
            sum1 = warpSum(sum1); sum2 = warpSum(sum2);
            float inv1 = 1.f/sum1, inv2 = lam/sum2;
            float* pcw = pc + (w*2+qi)*264;
            #pragma unroll
            for (int mi=0; mi<9; mi++){
                int m = l + (mi<<5);
                if (m < NN) pcw[m] = sc1[mi]*inv1 - sc2[mi]*inv2;
            }
            __syncwarp();
        }
        // ---- joint AV for the two queries ----
        const float* p0 = pc + (w*2+0)*264;
        const float* p1 = pc + (w*2+1)*264;
        float a0a=0.f, a0b=0.f, a1a=0.f, a1b=0.f;
        #pragma unroll 4
        for (int m=0; m<NN; m++){
            float va = vs[m*64+l], vb = vs[m*64+32+l];
            float q0p = p0[m], q1p = p1[m];
            a0a += q0p*va; a0b += q0p*vb;
            a1a += q1p*va; a1b += q1p*vb;
        }
        // ---- LN + write per query ----
        #pragma unroll
        for (int qi = 0; qi < 2; qi++) {
            int n = nb + qi;
            if (n >= NN) continue;     // uniform across warp
            float x0 = qi ? a1a : a0a;
            float x1 = qi ? a1b : a0b;
            float mean = warpSum(x0 + x1) * (1.f/64.f);
            float d0 = x0 - mean, d1 = x1 - mean;
            float var = warpSum(d0*d0 + d1*d1) * (1.f/64.f);
            float rstd = rsqrtf(var + 1e-5f);
            float* orow = st + (r0+n)*640 + h*64;
            orow[l]    = (d0*rstd*gl0 + bl0)*0.8f;   // *(1 - LAMBDA_INIT)
            orow[32+l] = (d1*rstd*gl1 + bl1)*0.8f;
        }
        __syncwarp();
    }
}

// ---------------- agg branch attention (pre-mix) ----------------
// grid (2, T, B), block 256. Pa cols: q 0..127, k 128..255, v 256..383
__global__ __launch_bounds__(256)
void agg_attn(const float* __restrict__ Pa, float* __restrict__ sx, int Ni)
{
    __shared__ float ks[64*65], vsh[64*64], ps[8*64], qs2[8*64];
    const int h = blockIdx.x, t = blockIdx.y, b = blockIdx.z;
    const size_t r0 = ((size_t)b*Tt + t) * Ni;
    const int tid = threadIdx.x;
    for (int i = tid; i < Ni*64; i += 256) {
        int m = i >> 6, d = i & 63;
        const float* row = Pa + (r0+m)*384 + h*64;
        ks[m*65+d]  = row[128 + d];
        vsh[i] = row[256 + d];
    }
    __syncthreads();
    const int w = tid>>5, l = tid&31;
    float* pw = ps  + w*64;
    float* qw = qs2 + w*64;
    for (int n = w; n < Ni; n += 8) {
        const float* qrow = Pa + (r0+n)*384 + h*64;
        qw[l] = qrow[l]; qw[32+l] = qrow[32+l];
        __syncwarp();
        float scv[2];
        #pragma unroll
        for (int mi=0; mi<2; mi++){
            int m = l + (mi<<5);
            float s = -1e30f;
            if (m < Ni){
                const float* kr = ks + m*65;
                float ts = 0.f;
                #pragma unroll
                for (int d=0; d<64; d++) ts += qw[d]*kr[d];
                s = ts * 0.125f;  // 64^-0.5
            }
            scv[mi] = s;
        }
        float mx = warpMax(fmaxf(scv[0], scv[1]));
        float sum = 0.f;
        #pragma unroll
        for (int mi=0; mi<2; mi++){
            int m = l + (mi<<5);
            if (m < Ni){ float e = __expf(scv[mi]-mx); pw[m] = e; sum += e; }
        }
        sum = warpSum(sum);
        __syncwarp();
        float aa = 0.f, ab = 0.f;
        for (int m=0; m<Ni; m++){
            float e = pw[m];
            aa += e*vsh[m*64+l];
            ab += e*vsh[m*64+32+l];
        }
        float inv = 1.f/sum;
        float* o = sx + ((((size_t)b*Tt+t)*2 + h)*Ni + n)*64;
        o[l] = aa*inv; o[32+l] = ab*inv;
        __syncwarp();
    }
}

// ---------------- mix agg branches through M0/M1 ----------------
__global__ __launch_bounds__(128)
void combine_sg(const float* __restrict__ sx0, const float* __restrict__ sx1,
                const float* __restrict__ M0, const float* __restrict__ M1,
                float* __restrict__ sg)
{
    const int n = blockIdx.x, t = blockIdx.y, b = blockIdx.z;
    const int j = threadIdx.x, h = j>>6, d = j&63;
    const size_t bt = (size_t)b*Tt + t;
    float acc = 0.f;
    const float* s0 = sx0 + (bt*2+h)*(32*64) + d;
    #pragma unroll 4
    for (int m=0; m<32; m++) acc += M0[m*NN+n] * s0[m*64];
    const float* s1 = sx1 + (bt*2+h)*(64*64) + d;
    #pragma unroll 4
    for (int m=0; m<64; m++) acc += M1[m*NN+n] * s1[m*64];
    sg[(bt*NN+n)*128 + j] = acc;
}

// ---------------- temporal attention (t_x + tgx fused) ----------------
// grid (N, B), block 64 (warp = head). P cols: qt 768, kt 896, vt 1024, ktg 1152, vtg 1280
__global__ __launch_bounds__(64)
void temporal_kernel(const float* __restrict__ P, const float* __restrict__ q_agg,
                     float* __restrict__ st, float* __restrict__ tgx)
{
    extern __shared__ float sm[];
    const int n = blockIdx.x, b = blockIdx.y;
    const int w = threadIdx.x >> 5, l = threadIdx.x & 31;  // w = head
    float* base = sm + w*6304;
    float* kts = base;                 // 24 x 65 (padded)
    float* vts = base + 1560;          // 24 x 64
    float* kgs = base + 3096;          // 24 x 65
    float* vgs = base + 4656;          // 24 x 64
    float* qsh = base + 6192;          // 64
    float* psh = base + 6256;          // 32
    for (int i=l; i<1536; i+=32){
        int t = i>>6, d = i&63;
        const float* row = P + (((size_t)b*Tt+t)*NN + n)*1408 + w*64;
        kts[t*65+d] = row[896+d];
        vts[i]      = row[1024+d];
        kgs[t*65+d] = row[1152+d];
        vgs[i]      = row[1280+d];
    }
    __syncwarp();
    // t_x: attention over time
    for (int tq=0; tq<Tt; tq++){
        const float* qrow = P + (((size_t)b*Tt+tq)*NN + n)*1408 + w*64 + 768;
        qsh[l] = qrow[l]; qsh[32+l] = qrow[32+l];
        __syncwarp();
        float s = -1e30f;
        if (l < Tt){
            const float* kr = kts + l*65;
            float ts = 0.f;
            #pragma unroll
            for (int d=0; d<64; d++) ts += qsh[d]*kr[d];
            s = ts*0.125f;
        }
        float mx = warpMax(s);
        float e = (l < Tt) ? __expf(s-mx) : 0.f;
        float sum = warpSum(e);
        psh[l] = e;
        __syncwarp();
        float aa = 0.f, ab = 0.f;
        #pragma unroll
        for (int ss=0; ss<Tt; ss++){
            float p = psh[ss];
            aa += p*vts[ss*64+l]; ab += p*vts[ss*64+32+l];
        }
        float inv = 1.f/sum;
        float* o = st + (((size_t)b*Tt+tq)*NN + n)*640 + 384 + w*64;
        o[l] = aa*inv; o[32+l] = ab*inv;
        __syncwarp();
    }
    // tgx: learned queries over time
    for (int sg_=0; sg_<12; sg_++){
        const float* qrow = q_agg + ((size_t)n*12 + sg_)*128 + w*64;
        qsh[l] = qrow[l]; qsh[32+l] = qrow[32+l];
        __syncwarp();
        float s = -1e30f;
        if (l < Tt){
            const float* kr = kgs + l*65;
            float ts = 0.f;
            #pragma unroll
            for (int d=0; d<64; d++) ts += qsh[d]*kr[d];
            s = ts*0.125f;
        }
        float mx = warpMax(s);
        float e = (l < Tt) ? __expf(s-mx) : 0.f;
        float sum = warpSum(e);
        psh[l] = e;
        __syncwarp();
        float aa = 0.f, ab = 0.f;
        #pragma unroll
        for (int ss=0; ss<Tt; ss++){
            float p = psh[ss];
            aa += p*vgs[ss*64+l]; ab += p*vgs[ss*64+32+l];
        }
        float inv = 1.f/sum;
        float* o = tgx + (((size_t)b*NN+n)*12 + sg_)*128 + w*64;
        o[l] = aa*inv; o[32+l] = ab*inv;
        __syncwarp();
    }
}

// ---------------- tg: mix tgx through tmp_map ----------------
__global__ __launch_bounds__(128)
void tg_scatter(const float* __restrict__ tmp_map, const float* __restrict__ tgx,
                float* __restrict__ st)
{
    const int n = blockIdx.x, t = blockIdx.y, b = blockIdx.z;
    const int j = threadIdx.x;
    const float* tm = tmp_map + (((size_t)b*NN + n)*Tt + t)*12;
    const float* g  = tgx + ((size_t)b*NN + n)*12*128 + j;
    float acc = 0.f;
    #pragma unroll
    for (int ss=0; ss<12; ss++) acc += tm[ss]*g[ss*128];
    st[(((size_t)b*Tt+t)*NN + n)*640 + 512 + j] = acc;
}

// ---------------- host ----------------
extern "C" void kernel_launch(void* const* d_in, const int* in_sizes, int n_in,
                              void* d_out, int out_size)
{
    (void)in_sizes; (void)n_in; (void)out_size;
    const float* x       = (const float*)d_in[0];
    const float* agg_x0  = (const float*)d_in[1];
    const float* agg_x1  = (const float*)d_in[2];
    const float* tmp_map = (const float*)d_in[3];

    float *P, *P0, *P1, *Wcat, *Wcat0, *Wcat1, *sx0, *sx1, *sg, *tgx, *st;
    cudaGetSymbolAddress((void**)&P,     g_P);
    cudaGetSymbolAddress((void**)&P0,    g_P0);
    cudaGetSymbolAddress((void**)&P1,    g_P1);
    cudaGetSymbolAddress((void**)&Wcat,  g_Wcat);
    cudaGetSymbolAddress((void**)&Wcat0, g_Wcat0);
    cudaGetSymbolAddress((void**)&Wcat1, g_Wcat1);
    cudaGetSymbolAddress((void**)&sx0,   g_sx0);
    cudaGetSymbolAddress((void**)&sx1,   g_sx1);
    cudaGetSymbolAddress((void**)&sg,    g_sg);
    cudaGetSymbolAddress((void**)&tgx,   g_tgx);
    cudaGetSymbolAddress((void**)&st,    g_st);

    // spatial smem: (263*36*2 + 263*64 + 16*264 + 8*64) floats = 40504 -> 162016 B
    cudaFuncSetAttribute(spatial_kernel,  cudaFuncAttributeMaxDynamicSharedMemorySize, 162016);
    cudaFuncSetAttribute(temporal_kernel, cudaFuncAttributeMaxDynamicSharedMemorySize, 50432);

    cudaStream_t s = 0;
    const size_t W512 = (size_t)512 * sizeof(float);
    // concat x-projection weights: [Wq_s, Wk_s, Wv_s, Wq_t, Wk_t, Wv_t, Wk_tg, Wv_tg]
    cudaMemcpyAsync(Wcat + (size_t)   0*512, d_in[4],  256*W512, cudaMemcpyDeviceToDevice, s);
    cudaMemcpyAsync(Wcat + (size_t) 256*512, d_in[5],  256*W512, cudaMemcpyDeviceToDevice, s);
    cudaMemcpyAsync(Wcat + (size_t) 512*512, d_in[6],  256*W512, cudaMemcpyDeviceToDevice, s);
    cudaMemcpyAsync(Wcat + (size_t) 768*512, d_in[23], 128*W512, cudaMemcpyDeviceToDevice, s);
    cudaMemcpyAsync(Wcat + (size_t) 896*512, d_in[24], 128*W512, cudaMemcpyDeviceToDevice, s);
    cudaMemcpyAsync(Wcat + (size_t)1024*512, d_in[25], 128*W512, cudaMemcpyDeviceToDevice, s);
    cudaMemcpyAsync(Wcat + (size_t)1152*512, d_in[27], 128*W512, cudaMemcpyDeviceToDevice, s);
    cudaMemcpyAsync(Wcat + (size_t)1280*512, d_in[28], 128*W512, cudaMemcpyDeviceToDevice, s);
    // agg weights
    cudaMemcpyAsync(Wcat0 + (size_t)  0*512, d_in[13], 128*W512, cudaMemcpyDeviceToDevice, s);
    cudaMemcpyAsync(Wcat0 + (size_t)128*512, d_in[14], 128*W512, cudaMemcpyDeviceToDevice, s);
    cudaMemcpyAsync(Wcat0 + (size_t)256*512, d_in[15], 128*W512, cudaMemcpyDeviceToDevice, s);
    cudaMemcpyAsync(Wcat1 + (size_t)  0*512, d_in[16], 128*W512, cudaMemcpyDeviceToDevice, s);
    cudaMemcpyAsync(Wcat1 + (size_t)128*512, d_in[17], 128*W512, cudaMemcpyDeviceToDevice, s);
    cudaMemcpyAsync(Wcat1 + (size_t)256*512, d_in[18], 128*W512, cudaMemcpyDeviceToDevice, s);

    lam_kernel<<<1,32,0,s>>>((const float*)d_in[7], (const float*)d_in[8],
                             (const float*)d_in[9], (const float*)d_in[10]);

    // projections (tf32 tensor cores, 3xTF32 compensated)
    gemm_tf32<<<dim3(11, 789), 256, 0, s>>>(x,      Wcat,  P,  nullptr, 50496, 1408, 512, 1408, 0);
    gemm_tf32<<<dim3(3,   96), 256, 0, s>>>(agg_x0, Wcat0, P0, nullptr,  6144,  384, 512,  384, 0);
    gemm_tf32<<<dim3(3,  192), 256, 0, s>>>(agg_x1, Wcat1, P1, nullptr, 12288,  384, 512,  384, 0);

    // branch 1: spatial diff attention -> st[:,0:256]
    spatial_kernel<<<dim3(4, Tt, Bb), 256, 162016, s>>>(P, st,
        (const float*)d_in[11], (const float*)d_in[12]);

    // branch 2: agg attention + mix + Wagg -> st[:,256:384]
    agg_attn<<<dim3(2, Tt, Bb), 256, 0, s>>>(P0, sx0, 32);
    agg_attn<<<dim3(2, Tt, Bb), 256, 0, s>>>(P1, sx1, 64);
    combine_sg<<<dim3(NN, Tt, Bb), 128, 0, s>>>(sx0, sx1,
        (const float*)d_in[19], (const float*)d_in[20], sg);
    gemm_tf32<<<dim3(1, 789), 256, 0, s>>>(sg, (const float*)d_in[21], st,
        (const float*)d_in[22], 50496, 128, 128, 640, 256);

    // branches 3+4: temporal attention -> st[:,384:512], tgx; then tg -> st[:,512:640]
    temporal_kernel<<<dim3(NN, Bb), 64, 50432, s>>>(P, (const float*)d_in[26], st, tgx);
    tg_scatter<<<dim3(NN, Tt, Bb), 128, 0, s>>>(tmp_map, tgx, st);

    // output projection
    gemm_tf32<<<dim3(4, 789), 256, 0, s>>>(st, (const float*)d_in[29], (float*)d_out,
        (const float*)d_in[30], 50496, 512, 640, 512, 0);
}

// round 5
// speedup vs baseline: 1.1810x; 1.1810x over previous
#include <cuda_runtime.h>
#include <cuda_bf16.h>
#include <math.h>
#include <stdint.h>

#define Bb 8
#define Tt 24
#define NN 263
#define Dd 512

// ---------------- scratch (static device globals; no allocation) ----------------
__device__ float g_P[71098368];      // 50496 x 1408  x-projections
__device__ float g_P0[2359296];      // 6144 x 384    agg0 projections
__device__ float g_P1[4718592];      // 12288 x 384   agg1 projections
__device__ float g_Wcat[720896];     // 1408 x 512
__device__ float g_Wcat0[196608];    // 384 x 512
__device__ float g_Wcat1[196608];    // 384 x 512
__device__ float g_sx0[786432];      // B*T*2*32*64
__device__ float g_sx1[1572864];     // B*T*2*64*64
__device__ float g_sg[6463488];      // 50496 x 128
__device__ float g_tgx[3231744];     // 8*263*12*128
__device__ float g_st[32317440];     // 50496 x 640
__device__ float g_lam;

// ---------------- helpers ----------------
__device__ __forceinline__ float warpMax(float v){
    #pragma unroll
    for (int o=16;o;o>>=1) v = fmaxf(v, __shfl_xor_sync(0xffffffffu, v, o));
    return v;
}
__device__ __forceinline__ float warpSum(float v){
    #pragma unroll
    for (int o=16;o;o>>=1) v += __shfl_xor_sync(0xffffffffu, v, o);
    return v;
}
// split two floats into packed bf16x2 hi and lo parts (lo = residual)
__device__ __forceinline__ void bf16_split2(float v0, float v1, uint32_t& hi, uint32_t& lo){
    __nv_bfloat16 h0 = __float2bfloat16(v0);
    __nv_bfloat16 h1 = __float2bfloat16(v1);
    float r0 = v0 - __bfloat162float(h0);
    float r1 = v1 - __bfloat162float(h1);
    __nv_bfloat16 l0 = __float2bfloat16(r0);
    __nv_bfloat16 l1 = __float2bfloat16(r1);
    hi = ((uint32_t)__bfloat16_as_ushort(h1) << 16) | (uint32_t)__bfloat16_as_ushort(h0);
    lo = ((uint32_t)__bfloat16_as_ushort(l1) << 16) | (uint32_t)__bfloat16_as_ushort(l0);
}

#define MMA_BF16(c, a, b) \
    asm volatile("mma.sync.aligned.m16n8k16.row.col.f32.bf16.bf16.f32 " \
        "{%0,%1,%2,%3},{%4,%5,%6,%7},{%8,%9},{%0,%1,%2,%3};" \
        : "+f"((c)[0]),"+f"((c)[1]),"+f"((c)[2]),"+f"((c)[3]) \
        : "r"((a)[0]),"r"((a)[1]),"r"((a)[2]),"r"((a)[3]),"r"((b)[0]),"r"((b)[1]))

// ---------------- lam scalar ----------------
__global__ void lam_kernel(const float* __restrict__ lq1, const float* __restrict__ lk1,
                           const float* __restrict__ lq2, const float* __restrict__ lk2)
{
    int l = threadIdx.x;
    float a = lq1[l]*lk1[l];
    float b = lq2[l]*lk2[l];
    a = warpSum(a); b = warpSum(b);
    if (l == 0) g_lam = expf(a) - expf(b) + 0.2f;   // LAMBDA_INIT = 0.2
}

// ---------------- bf16 tensor-core NT GEMM, 3-term compensated, double-buffered ----------
// C[m, coff+n] = sum_k A[m,k]*B[n,k] (+bias[n])
// Tile: BM=64, BN=128, BK=16. Requires M%64==0, N%128==0, K%16==0.
// smem layout: [kp 0..7][row], kp = k/2, each entry packs bf16(k even | k odd).
__global__ __launch_bounds__(256)
void gemm_bf16(const float* __restrict__ A, const float* __restrict__ B,
               float* __restrict__ C, const float* __restrict__ bias,
               int M, int N, int K, int ldc, int coff)
{
    __shared__ uint32_t Ah[2][8][72], Al[2][8][72];      // stride 72 (== 8 mod 32)
    __shared__ uint32_t Bh[2][8][136], Bl[2][8][136];    // stride 136 (== 8 mod 32)
    const int tid  = threadIdx.x;
    const int bm   = blockIdx.y * 64, bn = blockIdx.x * 128;
    const int warp = tid >> 5, lane = tid & 31;
    const int wm   = warp & 1, wn = warp >> 1;       // 2x4 warps, 32x32 each
    const int g    = lane >> 2, tg = lane & 3;

    const int ar  = tid & 63,  ac  = tid >> 6;   // A: row ar, k-chunk ac*4 (kp 2ac,2ac+1)
    const int br  = tid & 127, bcc = tid >> 7;   // B: row br, k-chunks bcc*4 and bcc*4+8

    float acc[2][4][4];
    #pragma unroll
    for (int i=0;i<2;i++)
        #pragma unroll
        for (int j=0;j<4;j++)
            #pragma unroll
            for (int q=0;q<4;q++) acc[i][j][q] = 0.f;

    const float* Ag  = A + (size_t)(bm + ar) * K + ac*4;
    const float* Bg0 = B + (size_t)(bn + br) * K + bcc*4;
    const float* Bg1 = Bg0 + 8;

    float4 av  = *(const float4*)Ag;
    float4 bv0 = *(const float4*)Bg0;
    float4 bv1 = *(const float4*)Bg1;

    // store tile into buffer bi
    auto storeAB = [&](int bi, const float4& a4, const float4& b4a, const float4& b4b){
        uint32_t h, l2;
        bf16_split2(a4.x, a4.y, h, l2);  Ah[bi][2*ac  ][ar] = h; Al[bi][2*ac  ][ar] = l2;
        bf16_split2(a4.z, a4.w, h, l2);  Ah[bi][2*ac+1][ar] = h; Al[bi][2*ac+1][ar] = l2;
        bf16_split2(b4a.x, b4a.y, h, l2); Bh[bi][2*bcc  ][br] = h; Bl[bi][2*bcc  ][br] = l2;
        bf16_split2(b4a.z, b4a.w, h, l2); Bh[bi][2*bcc+1][br] = h; Bl[bi][2*bcc+1][br] = l2;
        bf16_split2(b4b.x, b4b.y, h, l2); Bh[bi][2*bcc+4][br] = h; Bl[bi][2*bcc+4][br] = l2;
        bf16_split2(b4b.z, b4b.w, h, l2); Bh[bi][2*bcc+5][br] = h; Bl[bi][2*bcc+5][br] = l2;
    };

    storeAB(0, av, bv0, bv1);
    __syncthreads();

    const int nk = K >> 4;
    for (int kt = 0; kt < nk; kt++) {
        const int cur = kt & 1;
        const bool more = (kt + 1) < nk;
        if (more) {
            av  = *(const float4*)(Ag  + (kt+1)*16);
            bv0 = *(const float4*)(Bg0 + (kt+1)*16);
            bv1 = *(const float4*)(Bg1 + (kt+1)*16);
        }
        uint32_t afh[2][4], afl[2][4], bfh[4][2], bfl[4][2];
        #pragma unroll
        for (int mi=0; mi<2; mi++){
            int mr = wm*32 + mi*16;
            afh[mi][0] = Ah[cur][tg  ][mr+g  ];
            afh[mi][1] = Ah[cur][tg  ][mr+g+8];
            afh[mi][2] = Ah[cur][tg+4][mr+g  ];
            afh[mi][3] = Ah[cur][tg+4][mr+g+8];
            afl[mi][0] = Al[cur][tg  ][mr+g  ];
            afl[mi][1] = Al[cur][tg  ][mr+g+8];
            afl[mi][2] = Al[cur][tg+4][mr+g  ];
            afl[mi][3] = Al[cur][tg+4][mr+g+8];
        }
        #pragma unroll
        for (int ni=0; ni<4; ni++){
            int nc = wn*32 + ni*8;
            bfh[ni][0] = Bh[cur][tg  ][nc+g];
            bfh[ni][1] = Bh[cur][tg+4][nc+g];
            bfl[ni][0] = Bl[cur][tg  ][nc+g];
            bfl[ni][1] = Bl[cur][tg+4][nc+g];
        }
        #pragma unroll
        for (int mi=0; mi<2; mi++)
            #pragma unroll
            for (int ni=0; ni<4; ni++){
                MMA_BF16(acc[mi][ni], afh[mi], bfh[ni]);
                MMA_BF16(acc[mi][ni], afl[mi], bfh[ni]);
                MMA_BF16(acc[mi][ni], afh[mi], bfl[ni]);
            }
        if (more) {
            storeAB(cur ^ 1, av, bv0, bv1);
            __syncthreads();
        }
    }

    #pragma unroll
    for (int mi=0; mi<2; mi++){
        #pragma unroll
        for (int ni=0; ni<4; ni++){
            int gr = bm + wm*32 + mi*16 + g;
            int gc = bn + wn*32 + ni*8 + 2*tg;
            float b0 = bias ? bias[gc]   : 0.f;
            float b1 = bias ? bias[gc+1] : 0.f;
            float* Cp = C + (size_t)gr*ldc + coff + gc;
            Cp[0] = acc[mi][ni][0] + b0;
            Cp[1] = acc[mi][ni][1] + b1;
            Cp += (size_t)8*ldc;
            Cp[0] = acc[mi][ni][2] + b0;
            Cp[1] = acc[mi][ni][3] + b1;
        }
    }
}

// ---------------- spatial diff-attention (branch 1) ----------------
// grid (H=4, T, B), block 512 (16 warps, 2 queries per warp pass).
// P cols: q_s 0..255, k_s 256..511, v_s 512..767
__global__ __launch_bounds__(512)
void spatial_kernel(const float* __restrict__ P, float* __restrict__ st,
                    const float* __restrict__ ln_g, const float* __restrict__ ln_b)
{
    extern __shared__ float sm[];
    float* k1s = sm;                    // 263 x 36 (padded, conflict-free float4)
    float* k2s = k1s + NN*36;           // 263 x 36
    float* vs  = k2s + NN*36;           // 263 x 64
    float* pc  = vs  + NN*64;           // 32 slots x 264 (16 warps x 2 queries)
    float* qs  = pc  + 32*264;          // 16 x 64
    const int h = blockIdx.x, t = blockIdx.y, b = blockIdx.z;
    const size_t r0 = ((size_t)b*Tt + t) * NN;
    const int tid = threadIdx.x;

    for (int i = tid; i < NN*32; i += 512) {
        int m = i >> 5, d = i & 31;
        const float* row = P + (r0 + m) * 1408 + h*64;
        k1s[m*36+d] = row[256 + d];
        k2s[m*36+d] = row[288 + d];
    }
    for (int i = tid; i < NN*64; i += 512) {
        int m = i >> 6, e = i & 63;
        vs[i] = P[(r0+m)*1408 + 512 + h*64 + e];
    }
    __syncthreads();

    const float lam = g_lam;
    const int w = tid >> 5, l = tid & 31;
    float* qw  = qs + w*64;
    const float gl0 = ln_g[l], gl1 = ln_g[32+l];
    const float bl0 = ln_b[l], bl1 = ln_b[32+l];
    const float sc = 0.17677669529663687f;  // 32^-0.5

    for (int nb = 2*w; nb < 272; nb += 32) {
        // ---- score + softmax + combined-prob for two queries ----
        #pragma unroll
        for (int qi = 0; qi < 2; qi++) {
            int n = nb + qi;
            int nclamp = n < NN ? n : NN-1;
            const float* qrow = P + (r0+nclamp)*1408 + h*64;
            qw[l] = qrow[l]; qw[32+l] = qrow[32+l];
            __syncwarp();
            float sc1[9], sc2[9];
            #pragma unroll
            for (int mi=0; mi<9; mi++){ sc1[mi]=0.f; sc2[mi]=0.f; }
            #pragma unroll
            for (int dd=0; dd<8; dd++){
                float4 qa = *(const float4*)&qw[dd*4];
                float4 qb = *(const float4*)&qw[32+dd*4];
                #pragma unroll
                for (int mi=0; mi<9; mi++){
                    int m = l + (mi<<5);
                    int mc = m < NN ? m : 0;
                    float4 kA = *(const float4*)&k1s[mc*36 + dd*4];
                    float4 kB = *(const float4*)&k2s[mc*36 + dd*4];
                    sc1[mi] += qa.x*kA.x + qa.y*kA.y + qa.z*kA.z + qa.w*kA.w;
                    sc2[mi] += qb.x*kB.x + qb.y*kB.y + qb.z*kB.z + qb.w*kB.w;
                }
            }
            float mx1 = -1e30f, mx2 = -1e30f;
            #pragma unroll
            for (int mi=0; mi<9; mi++){
                int m = l + (mi<<5);
                if (m < NN){
                    sc1[mi] *= sc; sc2[mi] *= sc;
                    mx1 = fmaxf(mx1, sc1[mi]); mx2 = fmaxf(mx2, sc2[mi]);
                } else { sc1[mi] = -1e30f; sc2[mi] = -1e30f; }
            }
            mx1 = warpMax(mx1); mx2 = warpMax(mx2);
            float sum1 = 0.f, sum2 = 0.f;
            #pragma unroll
            for (int mi=0; mi<9; mi++){
                int m = l + (mi<<5);
                if (m < NN){
                    sc1[mi] = __expf(sc1[mi]-mx1);
                    sc2[mi] = __expf(sc2[mi]-mx2);
                    sum1 += sc1[mi]; sum2 += sc2[mi];
                }
            }
            sum1 = warpSum(sum1); sum2 = warpSum(sum2);
            float inv1 = 1.f/sum1, inv2 = lam/sum2;
            float* pcw = pc + (w*2+qi)*264;
            #pragma unroll
            for (int mi=0; mi<9; mi++){
                int m = l + (mi<<5);
                if (m < NN) pcw[m] = sc1[mi]*inv1 - sc2[mi]*inv2;
            }
            __syncwarp();
        }
        // ---- joint AV for the two queries ----
        const float* p0 = pc + (w*2+0)*264;
        const float* p1 = pc + (w*2+1)*264;
        float a0a=0.f, a0b=0.f, a1a=0.f, a1b=0.f;
        #pragma unroll 4
        for (int m=0; m<NN; m++){
            float va = vs[m*64+l], vb = vs[m*64+32+l];
            float q0p = p0[m], q1p = p1[m];
            a0a += q0p*va; a0b += q0p*vb;
            a1a += q1p*va; a1b += q1p*vb;
        }
        // ---- LN + write per query ----
        #pragma unroll
        for (int qi = 0; qi < 2; qi++) {
            int n = nb + qi;
            if (n >= NN) continue;     // uniform across warp
            float x0 = qi ? a1a : a0a;
            float x1 = qi ? a1b : a0b;
            float mean = warpSum(x0 + x1) * (1.f/64.f);
            float d0 = x0 - mean, d1 = x1 - mean;
            float var = warpSum(d0*d0 + d1*d1) * (1.f/64.f);
            float rstd = rsqrtf(var + 1e-5f);
            float* orow = st + (r0+n)*640 + h*64;
            orow[l]    = (d0*rstd*gl0 + bl0)*0.8f;   // *(1 - LAMBDA_INIT)
            orow[32+l] = (d1*rstd*gl1 + bl1)*0.8f;
        }
        __syncwarp();
    }
}

// ---------------- agg branch attention (pre-mix) ----------------
// grid (2, T, B), block 256. Pa cols: q 0..127, k 128..255, v 256..383
__global__ __launch_bounds__(256)
void agg_attn(const float* __restrict__ Pa, float* __restrict__ sx, int Ni)
{
    __shared__ float ks[64*65], vsh[64*64], ps[8*64], qs2[8*64];
    const int h = blockIdx.x, t = blockIdx.y, b = blockIdx.z;
    const size_t r0 = ((size_t)b*Tt + t) * Ni;
    const int tid = threadIdx.x;
    for (int i = tid; i < Ni*64; i += 256) {
        int m = i >> 6, d = i & 63;
        const float* row = Pa + (r0+m)*384 + h*64;
        ks[m*65+d]  = row[128 + d];
        vsh[i] = row[256 + d];
    }
    __syncthreads();
    const int w = tid>>5, l = tid&31;
    float* pw = ps  + w*64;
    float* qw = qs2 + w*64;
    for (int n = w; n < Ni; n += 8) {
        const float* qrow = Pa + (r0+n)*384 + h*64;
        qw[l] = qrow[l]; qw[32+l] = qrow[32+l];
        __syncwarp();
        float scv[2];
        #pragma unroll
        for (int mi=0; mi<2; mi++){
            int m = l + (mi<<5);
            float s = -1e30f;
            if (m < Ni){
                const float* kr = ks + m*65;
                float ts = 0.f;
                #pragma unroll
                for (int d=0; d<64; d++) ts += qw[d]*kr[d];
                s = ts * 0.125f;  // 64^-0.5
            }
            scv[mi] = s;
        }
        float mx = warpMax(fmaxf(scv[0], scv[1]));
        float sum = 0.f;
        #pragma unroll
        for (int mi=0; mi<2; mi++){
            int m = l + (mi<<5);
            if (m < Ni){ float e = __expf(scv[mi]-mx); pw[m] = e; sum += e; }
        }
        sum = warpSum(sum);
        __syncwarp();
        float aa = 0.f, ab = 0.f;
        for (int m=0; m<Ni; m++){
            float e = pw[m];
            aa += e*vsh[m*64+l];
            ab += e*vsh[m*64+32+l];
        }
        float inv = 1.f/sum;
        float* o = sx + ((((size_t)b*Tt+t)*2 + h)*Ni + n)*64;
        o[l] = aa*inv; o[32+l] = ab*inv;
        __syncwarp();
    }
}

// ---------------- mix agg branches through M0/M1 ----------------
__global__ __launch_bounds__(128)
void combine_sg(const float* __restrict__ sx0, const float* __restrict__ sx1,
                const float* __restrict__ M0, const float* __restrict__ M1,
                float* __restrict__ sg)
{
    const int n = blockIdx.x, t = blockIdx.y, b = blockIdx.z;
    const int j = threadIdx.x, h = j>>6, d = j&63;
    const size_t bt = (size_t)b*Tt + t;
    float acc = 0.f;
    const float* s0 = sx0 + (bt*2+h)*(32*64) + d;
    #pragma unroll 4
    for (int m=0; m<32; m++) acc += M0[m*NN+n] * s0[m*64];
    const float* s1 = sx1 + (bt*2+h)*(64*64) + d;
    #pragma unroll 4
    for (int m=0; m<64; m++) acc += M1[m*NN+n] * s1[m*64];
    sg[(bt*NN+n)*128 + j] = acc;
}

// ---------------- temporal attention (t_x + tgx fused) ----------------
// grid (N, B), block 128: warp = (half, head). half splits the query loops.
// P cols: qt 768, kt 896, vt 1024, ktg 1152, vtg 1280
__global__ __launch_bounds__(128)
void temporal_kernel(const float* __restrict__ P, const float* __restrict__ q_agg,
                     float* __restrict__ st, float* __restrict__ tgx)
{
    extern __shared__ float sm[];
    const int n = blockIdx.x, b = blockIdx.y;
    const int wid = threadIdx.x >> 5, l = threadIdx.x & 31;
    const int w = wid & 1;        // head
    const int half = wid >> 1;    // query-range half
    float* base = sm + w*6240;
    float* kts = base;                 // 24 x 65 (padded)
    float* vts = base + 1560;          // 24 x 64
    float* kgs = base + 3096;          // 24 x 65
    float* vgs = base + 4656;          // 24 x 64
    float* qp  = sm + 2*6240 + wid*96;
    float* qsh = qp;                   // 64
    float* psh = qp + 64;              // 32
    // two warps per head load that head's K/V (each loads half)
    for (int i = half*768 + l; i < half*768 + 768; i += 32){
        int t = i>>6, d = i&63;
        const float* row = P + (((size_t)b*Tt+t)*NN + n)*1408 + w*64;
        kts[t*65+d] = row[896+d];
        vts[t*64+d] = row[1024+d];
        kgs[t*65+d] = row[1152+d];
        vgs[t*64+d] = row[1280+d];
    }
    for (int i = half*768 + 1536 + l; i < half*768 + 1536 + 768; i += 32){
        int ii = i - 1536;
        int t = ii>>6, d = ii&63;
        const float* row = P + (((size_t)b*Tt+t)*NN + n)*1408 + w*64;
        (void)row;
    }
    __syncthreads();
    // t_x: attention over time (each warp handles 12 of 24 queries)
    for (int tq = half*12; tq < half*12 + 12; tq++){
        const float* qrow = P + (((size_t)b*Tt+tq)*NN + n)*1408 + w*64 + 768;
        qsh[l] = qrow[l]; qsh[32+l] = qrow[32+l];
        __syncwarp();
        float s = -1e30f;
        if (l < Tt){
            const float* kr = kts + l*65;
            float ts = 0.f;
            #pragma unroll
            for (int d=0; d<64; d++) ts += qsh[d]*kr[d];
            s = ts*0.125f;
        }
        float mx = warpMax(s);
        float e = (l < Tt) ? __expf(s-mx) : 0.f;
        float sum = warpSum(e);
        psh[l] = e;
        __syncwarp();
        float aa = 0.f, ab = 0.f;
        #pragma unroll
        for (int ss=0; ss<Tt; ss++){
            float p = psh[ss];
            aa += p*vts[ss*64+l]; ab += p*vts[ss*64+32+l];
        }
        float inv = 1.f/sum;
        float* o = st + (((size_t)b*Tt+tq)*NN + n)*640 + 384 + w*64;
        o[l] = aa*inv; o[32+l] = ab*inv;
        __syncwarp();
    }
    // tgx: learned queries over time (each warp handles 6 of 12)
    for (int sg_ = half*6; sg_ < half*6 + 6; sg_++){
        const float* qrow = q_agg + ((size_t)n*12 + sg_)*128 + w*64;
        qsh[l] = qrow[l]; qsh[32+l] = qrow[32+l];
        __syncwarp();
        float s = -1e30f;
        if (l < Tt){
            const float* kr = kgs + l*65;
            float ts = 0.f;
            #pragma unroll
            for (int d=0; d<64; d++) ts += qsh[d]*kr[d];
            s = ts*0.125f;
        }
        float mx = warpMax(s);
        float e = (l < Tt) ? __expf(s-mx) : 0.f;
        float sum = warpSum(e);
        psh[l] = e;
        __syncwarp();
        float aa = 0.f, ab = 0.f;
        #pragma unroll
        for (int ss=0; ss<Tt; ss++){
            float p = psh[ss];
            aa += p*vgs[ss*64+l]; ab += p*vgs[ss*64+32+l];
        }
        float inv = 1.f/sum;
        float* o = tgx + (((size_t)b*NN+n)*12 + sg_)*128 + w*64;
        o[l] = aa*inv; o[32+l] = ab*inv;
        __syncwarp();
    }
}

// ---------------- tg: mix tgx through tmp_map ----------------
__global__ __launch_bounds__(128)
void tg_scatter(const float* __restrict__ tmp_map, const float* __restrict__ tgx,
                float* __restrict__ st)
{
    const int n = blockIdx.x, t = blockIdx.y, b = blockIdx.z;
    const int j = threadIdx.x;
    const float* tm = tmp_map + (((size_t)b*NN + n)*Tt + t)*12;
    const float* g  = tgx + ((size_t)b*NN + n)*12*128 + j;
    float acc = 0.f;
    #pragma unroll
    for (int ss=0; ss<12; ss++) acc += tm[ss]*g[ss*128];
    st[(((size_t)b*Tt+t)*NN + n)*640 + 512 + j] = acc;
}

// ---------------- host ----------------
extern "C" void kernel_launch(void* const* d_in, const int* in_sizes, int n_in,
                              void* d_out, int out_size)
{
    (void)in_sizes; (void)n_in; (void)out_size;
    const float* x       = (const float*)d_in[0];
    const float* agg_x0  = (const float*)d_in[1];
    const float* agg_x1  = (const float*)d_in[2];
    const float* tmp_map = (const float*)d_in[3];

    float *P, *P0, *P1, *Wcat, *Wcat0, *Wcat1, *sx0, *sx1, *sg, *tgx, *st;
    cudaGetSymbolAddress((void**)&P,     g_P);
    cudaGetSymbolAddress((void**)&P0,    g_P0);
    cudaGetSymbolAddress((void**)&P1,    g_P1);
    cudaGetSymbolAddress((void**)&Wcat,  g_Wcat);
    cudaGetSymbolAddress((void**)&Wcat0, g_Wcat0);
    cudaGetSymbolAddress((void**)&Wcat1, g_Wcat1);
    cudaGetSymbolAddress((void**)&sx0,   g_sx0);
    cudaGetSymbolAddress((void**)&sx1,   g_sx1);
    cudaGetSymbolAddress((void**)&sg,    g_sg);
    cudaGetSymbolAddress((void**)&tgx,   g_tgx);
    cudaGetSymbolAddress((void**)&st,    g_st);

    // spatial smem: (263*36*2 + 263*64 + 32*264 + 16*64) floats = 45240 -> 180960 B
    cudaFuncSetAttribute(spatial_kernel,  cudaFuncAttributeMaxDynamicSharedMemorySize, 180960);
    // temporal smem: (2*6240 + 4*96) floats = 12864 -> 51456 B
    cudaFuncSetAttribute(temporal_kernel, cudaFuncAttributeMaxDynamicSharedMemorySize, 51456);

    cudaStream_t s = 0;
    const size_t W512 = (size_t)512 * sizeof(float);
    // concat x-projection weights: [Wq_s, Wk_s, Wv_s, Wq_t, Wk_t, Wv_t, Wk_tg, Wv_tg]
    cudaMemcpyAsync(Wcat + (size_t)   0*512, d_in[4],  256*W512, cudaMemcpyDeviceToDevice, s);
    cudaMemcpyAsync(Wcat + (size_t) 256*512, d_in[5],  256*W512, cudaMemcpyDeviceToDevice, s);
    cudaMemcpyAsync(Wcat + (size_t) 512*512, d_in[6],  256*W512, cudaMemcpyDeviceToDevice, s);
    cudaMemcpyAsync(Wcat + (size_t) 768*512, d_in[23], 128*W512, cudaMemcpyDeviceToDevice, s);
    cudaMemcpyAsync(Wcat + (size_t) 896*512, d_in[24], 128*W512, cudaMemcpyDeviceToDevice, s);
    cudaMemcpyAsync(Wcat + (size_t)1024*512, d_in[25], 128*W512, cudaMemcpyDeviceToDevice, s);
    cudaMemcpyAsync(Wcat + (size_t)1152*512, d_in[27], 128*W512, cudaMemcpyDeviceToDevice, s);
    cudaMemcpyAsync(Wcat + (size_t)1280*512, d_in[28], 128*W512, cudaMemcpyDeviceToDevice, s);
    // agg weights
    cudaMemcpyAsync(Wcat0 + (size_t)  0*512, d_in[13], 128*W512, cudaMemcpyDeviceToDevice, s);
    cudaMemcpyAsync(Wcat0 + (size_t)128*512, d_in[14], 128*W512, cudaMemcpyDeviceToDevice, s);
    cudaMemcpyAsync(Wcat0 + (size_t)256*512, d_in[15], 128*W512, cudaMemcpyDeviceToDevice, s);
    cudaMemcpyAsync(Wcat1 + (size_t)  0*512, d_in[16], 128*W512, cudaMemcpyDeviceToDevice, s);
    cudaMemcpyAsync(Wcat1 + (size_t)128*512, d_in[17], 128*W512, cudaMemcpyDeviceToDevice, s);
    cudaMemcpyAsync(Wcat1 + (size_t)256*512, d_in[18], 128*W512, cudaMemcpyDeviceToDevice, s);

    lam_kernel<<<1,32,0,s>>>((const float*)d_in[7], (const float*)d_in[8],
                             (const float*)d_in[9], (const float*)d_in[10]);

    // projections (bf16 tensor cores, 3-term compensated)
    gemm_bf16<<<dim3(11, 789), 256, 0, s>>>(x,      Wcat,  P,  nullptr, 50496, 1408, 512, 1408, 0);
    gemm_bf16<<<dim3(3,   96), 256, 0, s>>>(agg_x0, Wcat0, P0, nullptr,  6144,  384, 512,  384, 0);
    gemm_bf16<<<dim3(3,  192), 256, 0, s>>>(agg_x1, Wcat1, P1, nullptr, 12288,  384, 512,  384, 0);

    // branch 1: spatial diff attention -> st[:,0:256]
    spatial_kernel<<<dim3(4, Tt, Bb), 512, 180960, s>>>(P, st,
        (const float*)d_in[11], (const float*)d_in[12]);

    // branch 2: agg attention + mix + Wagg -> st[:,256:384]
    agg_attn<<<dim3(2, Tt, Bb), 256, 0, s>>>(P0, sx0, 32);
    agg_attn<<<dim3(2, Tt, Bb), 256, 0, s>>>(P1, sx1, 64);
    combine_sg<<<dim3(NN, Tt, Bb), 128, 0, s>>>(sx0, sx1,
        (const float*)d_in[19], (const float*)d_in[20], sg);
    gemm_bf16<<<dim3(1, 789), 256, 0, s>>>(sg, (const float*)d_in[21], st,
        (const float*)d_in[22], 50496, 128, 128, 640, 256);

    // branches 3+4: temporal attention -> st[:,384:512], tgx; then tg -> st[:,512:640]
    temporal_kernel<<<dim3(NN, Bb), 128, 51456, s>>>(P, (const float*)d_in[26], st, tgx);
    tg_scatter<<<dim3(NN, Tt, Bb), 128, 0, s>>>(tmp_map, tgx, st);

    // output projection
    gemm_bf16<<<dim3(4, 789), 256, 0, s>>>(st, (const float*)d_in[29], (float*)d_out,
        (const float*)d_in[30], 50496, 512, 640, 512, 0);
}

// round 6
// speedup vs baseline: 1.6919x; 1.4326x over previous
#include <cuda_runtime.h>
#include <cuda_bf16.h>
#include <math.h>
#include <stdint.h>

#define Bb 8
#define Tt 24
#define NN 263
#define Dd 512

// ---------------- scratch (static device globals; no allocation) ----------------
__device__ float g_P[71098368];      // 50496 x 1408  x-projections
__device__ float g_P0[2359296];      // 6144 x 384    agg0 projections
__device__ float g_P1[4718592];      // 12288 x 384   agg1 projections
__device__ float g_Wcat[720896];     // 1408 x 512
__device__ float g_Wcat0[196608];    // 384 x 512
__device__ float g_Wcat1[196608];    // 384 x 512
__device__ float g_sx0[786432];      // B*T*2*32*64
__device__ float g_sx1[1572864];     // B*T*2*64*64
__device__ float g_sg[6463488];      // 50496 x 128
__device__ float g_tgx[3231744];     // 8*263*12*128
__device__ float g_st[32317440];     // 50496 x 640
__device__ float g_lam;

// bf16 hi/lo planes
__device__ __nv_bfloat16 g_xh[25853952],  g_xl[25853952];    // 50496 x 512
__device__ __nv_bfloat16 g_a0h[3145728],  g_a0l[3145728];    // 6144 x 512
__device__ __nv_bfloat16 g_a1h[6291456],  g_a1l[6291456];    // 12288 x 512
__device__ __nv_bfloat16 g_Wh[720896],    g_Wl[720896];      // 1408 x 512
__device__ __nv_bfloat16 g_W0h[196608],   g_W0l[196608];     // 384 x 512
__device__ __nv_bfloat16 g_W1h[196608],   g_W1l[196608];     // 384 x 512
__device__ __nv_bfloat16 g_sgh[6463488],  g_sgl[6463488];    // 50496 x 128
__device__ __nv_bfloat16 g_Wah[16384],    g_Wal[16384];      // 128 x 128
__device__ __nv_bfloat16 g_sth[32317440], g_stl[32317440];   // 50496 x 640
__device__ __nv_bfloat16 g_Woh[327680],   g_Wol[327680];     // 512 x 640

// ---------------- helpers ----------------
__device__ __forceinline__ float warpMax(float v){
    #pragma unroll
    for (int o=16;o;o>>=1) v = fmaxf(v, __shfl_xor_sync(0xffffffffu, v, o));
    return v;
}
__device__ __forceinline__ float warpSum(float v){
    #pragma unroll
    for (int o=16;o;o>>=1) v += __shfl_xor_sync(0xffffffffu, v, o);
    return v;
}
__device__ __forceinline__ uint32_t smem_u32(const void* p){
    return (uint32_t)__cvta_generic_to_shared(p);
}
__device__ __forceinline__ void cp16(uint32_t dst, const void* src){
    asm volatile("cp.async.cg.shared.global [%0], [%1], 16;" :: "r"(dst), "l"(src));
}

#define MMA_BF16(c, a, b) \
    asm volatile("mma.sync.aligned.m16n8k16.row.col.f32.bf16.bf16.f32 " \
        "{%0,%1,%2,%3},{%4,%5,%6,%7},{%8,%9},{%0,%1,%2,%3};" \
        : "+f"((c)[0]),"+f"((c)[1]),"+f"((c)[2]),"+f"((c)[3]) \
        : "r"((a)[0]),"r"((a)[1]),"r"((a)[2]),"r"((a)[3]),"r"((b)[0]),"r"((b)[1]))

#define LDSM4(r0,r1,r2,r3,addr) \
    asm volatile("ldmatrix.sync.aligned.m8n8.x4.shared.b16 {%0,%1,%2,%3}, [%4];" \
        : "=r"(r0),"=r"(r1),"=r"(r2),"=r"(r3) : "r"(addr))

// ---------------- split fp32 -> bf16 hi/lo planes ----------------
__global__ __launch_bounds__(256)
void split_bf16(const float* __restrict__ src, __nv_bfloat16* __restrict__ hi,
                __nv_bfloat16* __restrict__ lo, int n)
{
    int i = (blockIdx.x*256 + threadIdx.x)*4;
    if (i >= n) return;
    float4 v = *(const float4*)(src+i);
    __nv_bfloat16 h0=__float2bfloat16(v.x), h1=__float2bfloat16(v.y);
    __nv_bfloat16 h2=__float2bfloat16(v.z), h3=__float2bfloat16(v.w);
    __nv_bfloat16 l0=__float2bfloat16(v.x-__bfloat162float(h0));
    __nv_bfloat16 l1=__float2bfloat16(v.y-__bfloat162float(h1));
    __nv_bfloat16 l2=__float2bfloat16(v.z-__bfloat162float(h2));
    __nv_bfloat16 l3=__float2bfloat16(v.w-__bfloat162float(h3));
    uint32_t wh0 = ((uint32_t)__bfloat16_as_ushort(h1)<<16)|__bfloat16_as_ushort(h0);
    uint32_t wh1 = ((uint32_t)__bfloat16_as_ushort(h3)<<16)|__bfloat16_as_ushort(h2);
    uint32_t wl0 = ((uint32_t)__bfloat16_as_ushort(l1)<<16)|__bfloat16_as_ushort(l0);
    uint32_t wl1 = ((uint32_t)__bfloat16_as_ushort(l3)<<16)|__bfloat16_as_ushort(l2);
    *(uint2*)(hi+i) = make_uint2(wh0, wh1);
    *(uint2*)(lo+i) = make_uint2(wl0, wl1);
}

// ---------------- lam scalar ----------------
__global__ void lam_kernel(const float* __restrict__ lq1, const float* __restrict__ lk1,
                           const float* __restrict__ lq2, const float* __restrict__ lk2)
{
    int l = threadIdx.x;
    float a = lq1[l]*lk1[l];
    float b = lq2[l]*lk2[l];
    a = warpSum(a); b = warpSum(b);
    if (l == 0) g_lam = expf(a) - expf(b) + 0.2f;   // LAMBDA_INIT = 0.2
}

// ---------------- bf16 tensor-core NT GEMM over 3 plane-pairs ----------------
// C[m, coff+n] = sum over (Ah*Bh + Al*Bh + Ah*Bl), A/B bf16 planes, NT.
// BM=64, BN=128, BK=64; 256 threads (8 warps, 2m x 4n, warp tile 32x32).
// smem rows padded to 144B (128B data + 16B) -> ldmatrix conflict-free.
__global__ __launch_bounds__(256, 2)
void gemm_tc(const __nv_bfloat16* __restrict__ Ah, const __nv_bfloat16* __restrict__ Al,
             const __nv_bfloat16* __restrict__ Bh, const __nv_bfloat16* __restrict__ Bl,
             float* __restrict__ C, const float* __restrict__ bias,
             int M, int N, int K, int ldc, int coff)
{
    extern __shared__ __align__(16) uint8_t smem[];
    uint8_t* smA = smem;                 // 2 x 64 x 144
    uint8_t* smB = smem + 2*64*144;      // 2 x 128 x 144
    const int tid = threadIdx.x;
    const int bm = blockIdx.y*64, bn = blockIdx.x*128;
    const int warp = tid>>5, lane = tid&31;
    const int wm = warp & 1, wn = warp >> 1;
    const int g = lane>>2, tg = lane&3;

    const int nkt  = K >> 6;
    const int ntot = 3*nkt;

    const int lr = tid >> 3, lc = tid & 7;   // cp.async map: row, 16B chunk

    float acc[2][4][4];
    #pragma unroll
    for (int i=0;i<2;i++)
        #pragma unroll
        for (int j=0;j<4;j++)
            #pragma unroll
            for (int q=0;q<4;q++) acc[i][j][q] = 0.f;

    auto issue_tile = [&](int t, int buf){
        int pass = t / nkt;
        int k0   = (t - pass*nkt) << 6;
        const __nv_bfloat16* Ap = (pass==1) ? Al : Ah;
        const __nv_bfloat16* Bp = (pass==2) ? Bl : Bh;
        uint8_t* da = smA + buf*(64*144);
        uint8_t* db = smB + buf*(128*144);
        cp16(smem_u32(da + lr*144 + lc*16),        Ap + (size_t)(bm+lr)*K    + k0 + lc*8);
        cp16(smem_u32(da + (lr+32)*144 + lc*16),   Ap + (size_t)(bm+lr+32)*K + k0 + lc*8);
        #pragma unroll
        for (int i=0;i<4;i++){
            int r = lr + i*32;
            cp16(smem_u32(db + r*144 + lc*16),     Bp + (size_t)(bn+r)*K     + k0 + lc*8);
        }
        asm volatile("cp.async.commit_group;");
    };

    issue_tile(0, 0);
    issue_tile(1, 1);

    // per-lane ldmatrix base geometry
    const int arow = wm*32 + (lane & 15);
    const int ach  = lane >> 4;                       // 0/1 -> +chunk
    const int brow = wn*32 + (lane & 7) + ((lane >> 4) << 3);
    const int bch  = (lane >> 3) & 1;

    for (int t = 0; t < ntot; t++){
        const int buf = t & 1;
        if (t + 1 < ntot) { asm volatile("cp.async.wait_group 1;"); }
        else              { asm volatile("cp.async.wait_group 0;"); }
        __syncthreads();
        const uint8_t* da = smA + buf*(64*144);
        const uint8_t* db = smB + buf*(128*144);
        #pragma unroll
        for (int kk = 0; kk < 4; kk++){
            uint32_t af[2][4];
            #pragma unroll
            for (int mi=0; mi<2; mi++){
                uint32_t ad = smem_u32(da + (arow + mi*16)*144 + (2*kk + ach)*16);
                LDSM4(af[mi][0], af[mi][1], af[mi][2], af[mi][3], ad);
            }
            uint32_t bf[4][2];
            #pragma unroll
            for (int ni2=0; ni2<2; ni2++){
                uint32_t bd = smem_u32(db + (brow + ni2*16)*144 + (2*kk + bch)*16);
                uint32_t r0,r1,r2,r3;
                LDSM4(r0,r1,r2,r3, bd);
                bf[2*ni2][0]=r0;   bf[2*ni2][1]=r1;
                bf[2*ni2+1][0]=r2; bf[2*ni2+1][1]=r3;
            }
            #pragma unroll
            for (int mi=0; mi<2; mi++)
                #pragma unroll
                for (int ni=0; ni<4; ni++)
                    MMA_BF16(acc[mi][ni], af[mi], bf[ni]);
        }
        __syncthreads();
        if (t + 2 < ntot) issue_tile(t+2, buf);
    }

    #pragma unroll
    for (int mi=0; mi<2; mi++){
        #pragma unroll
        for (int ni=0; ni<4; ni++){
            int gr = bm + wm*32 + mi*16 + g;
            int gc = bn + wn*32 + ni*8 + 2*tg;
            float b0 = bias ? bias[gc]   : 0.f;
            float b1 = bias ? bias[gc+1] : 0.f;
            float* Cp = C + (size_t)gr*ldc + coff + gc;
            Cp[0] = acc[mi][ni][0] + b0;
            Cp[1] = acc[mi][ni][1] + b1;
            Cp += (size_t)8*ldc;
            Cp[0] = acc[mi][ni][2] + b0;
            Cp[1] = acc[mi][ni][3] + b1;
        }
    }
}

// ---------------- spatial diff-attention (branch 1) ----------------
__global__ __launch_bounds__(512)
void spatial_kernel(const float* __restrict__ P, float* __restrict__ st,
                    const float* __restrict__ ln_g, const float* __restrict__ ln_b)
{
    extern __shared__ float sm[];
    float* k1s = sm;                    // 263 x 36
    float* k2s = k1s + NN*36;           // 263 x 36
    float* vs  = k2s + NN*36;           // 263 x 64
    float* pc  = vs  + NN*64;           // 32 x 264
    float* qs  = pc  + 32*264;          // 16 x 64
    const int h = blockIdx.x, t = blockIdx.y, b = blockIdx.z;
    const size_t r0 = ((size_t)b*Tt + t) * NN;
    const int tid = threadIdx.x;

    for (int i = tid; i < NN*32; i += 512) {
        int m = i >> 5, d = i & 31;
        const float* row = P + (r0 + m) * 1408 + h*64;
        k1s[m*36+d] = row[256 + d];
        k2s[m*36+d] = row[288 + d];
    }
    for (int i = tid; i < NN*64; i += 512) {
        int m = i >> 6, e = i & 63;
        vs[i] = P[(r0+m)*1408 + 512 + h*64 + e];
    }
    __syncthreads();

    const float lam = g_lam;
    const int w = tid >> 5, l = tid & 31;
    float* qw  = qs + w*64;
    const float gl0 = ln_g[l], gl1 = ln_g[32+l];
    const float bl0 = ln_b[l], bl1 = ln_b[32+l];
    const float sc = 0.17677669529663687f;

    for (int nb = 2*w; nb < 272; nb += 32) {
        #pragma unroll
        for (int qi = 0; qi < 2; qi++) {
            int n = nb + qi;
            int nclamp = n < NN ? n : NN-1;
            const float* qrow = P + (r0+nclamp)*1408 + h*64;
            qw[l] = qrow[l]; qw[32+l] = qrow[32+l];
            __syncwarp();
            float sc1[9], sc2[9];
            #pragma unroll
            for (int mi=0; mi<9; mi++){ sc1[mi]=0.f; sc2[mi]=0.f; }
            #pragma unroll
            for (int dd=0; dd<8; dd++){
                float4 qa = *(const float4*)&qw[dd*4];
                float4 qb = *(const float4*)&qw[32+dd*4];
                #pragma unroll
                for (int mi=0; mi<9; mi++){
                    int m = l + (mi<<5);
                    int mc = m < NN ? m : 0;
                    float4 kA = *(const float4*)&k1s[mc*36 + dd*4];
                    float4 kB = *(const float4*)&k2s[mc*36 + dd*4];
                    sc1[mi] += qa.x*kA.x + qa.y*kA.y + qa.z*kA.z + qa.w*kA.w;
                    sc2[mi] += qb.x*kB.x + qb.y*kB.y + qb.z*kB.z + qb.w*kB.w;
                }
            }
            float mx1 = -1e30f, mx2 = -1e30f;
            #pragma unroll
            for (int mi=0; mi<9; mi++){
                int m = l + (mi<<5);
                if (m < NN){
                    sc1[mi] *= sc; sc2[mi] *= sc;
                    mx1 = fmaxf(mx1, sc1[mi]); mx2 = fmaxf(mx2, sc2[mi]);
                } else { sc1[mi] = -1e30f; sc2[mi] = -1e30f; }
            }
            mx1 = warpMax(mx1); mx2 = warpMax(mx2);
            float sum1 = 0.f, sum2 = 0.f;
            #pragma unroll
            for (int mi=0; mi<9; mi++){
                int m = l + (mi<<5);
                if (m < NN){
                    sc1[mi] = __expf(sc1[mi]-mx1);
                    sc2[mi] = __expf(sc2[mi]-mx2);
                    sum1 += sc1[mi]; sum2 += sc2[mi];
                }
            }
            sum1 = warpSum(sum1); sum2 = warpSum(sum2);
            float inv1 = 1.f/sum1, inv2 = lam/sum2;
            float* pcw = pc + (w*2+qi)*264;
            #pragma unroll
            for (int mi=0; mi<9; mi++){
                int m = l + (mi<<5);
                if (m < NN) pcw[m] = sc1[mi]*inv1 - sc2[mi]*inv2;
            }
            __syncwarp();
        }
        const float* p0 = pc + (w*2+0)*264;
        const float* p1 = pc + (w*2+1)*264;
        float a0a=0.f, a0b=0.f, a1a=0.f, a1b=0.f;
        #pragma unroll 4
        for (int m=0; m<NN; m++){
            float va = vs[m*64+l], vb = vs[m*64+32+l];
            float q0p = p0[m], q1p = p1[m];
            a0a += q0p*va; a0b += q0p*vb;
            a1a += q1p*va; a1b += q1p*vb;
        }
        #pragma unroll
        for (int qi = 0; qi < 2; qi++) {
            int n = nb + qi;
            if (n >= NN) continue;
            float x0 = qi ? a1a : a0a;
            float x1 = qi ? a1b : a0b;
            float mean = warpSum(x0 + x1) * (1.f/64.f);
            float d0 = x0 - mean, d1 = x1 - mean;
            float var = warpSum(d0*d0 + d1*d1) * (1.f/64.f);
            float rstd = rsqrtf(var + 1e-5f);
            float* orow = st + (r0+n)*640 + h*64;
            orow[l]    = (d0*rstd*gl0 + bl0)*0.8f;
            orow[32+l] = (d1*rstd*gl1 + bl1)*0.8f;
        }
        __syncwarp();
    }
}

// ---------------- agg branch attention (pre-mix) ----------------
__global__ __launch_bounds__(256)
void agg_attn(const float* __restrict__ Pa, float* __restrict__ sx, int Ni)
{
    __shared__ float ks[64*65], vsh[64*64], ps[8*64], qs2[8*64];
    const int h = blockIdx.x, t = blockIdx.y, b = blockIdx.z;
    const size_t r0 = ((size_t)b*Tt + t) * Ni;
    const int tid = threadIdx.x;
    for (int i = tid; i < Ni*64; i += 256) {
        int m = i >> 6, d = i & 63;
        const float* row = Pa + (r0+m)*384 + h*64;
        ks[m*65+d]  = row[128 + d];
        vsh[i] = row[256 + d];
    }
    __syncthreads();
    const int w = tid>>5, l = tid&31;
    float* pw = ps  + w*64;
    float* qw = qs2 + w*64;
    for (int n = w; n < Ni; n += 8) {
        const float* qrow = Pa + (r0+n)*384 + h*64;
        qw[l] = qrow[l]; qw[32+l] = qrow[32+l];
        __syncwarp();
        float scv[2];
        #pragma unroll
        for (int mi=0; mi<2; mi++){
            int m = l + (mi<<5);
            float s = -1e30f;
            if (m < Ni){
                const float* kr = ks + m*65;
                float ts = 0.f;
                #pragma unroll
                for (int d=0; d<64; d++) ts += qw[d]*kr[d];
                s = ts * 0.125f;
            }
            scv[mi] = s;
        }
        float mx = warpMax(fmaxf(scv[0], scv[1]));
        float sum = 0.f;
        #pragma unroll
        for (int mi=0; mi<2; mi++){
            int m = l + (mi<<5);
            if (m < Ni){ float e = __expf(scv[mi]-mx); pw[m] = e; sum += e; }
        }
        sum = warpSum(sum);
        __syncwarp();
        float aa = 0.f, ab = 0.f;
        for (int m=0; m<Ni; m++){
            float e = pw[m];
            aa += e*vsh[m*64+l];
            ab += e*vsh[m*64+32+l];
        }
        float inv = 1.f/sum;
        float* o = sx + ((((size_t)b*Tt+t)*2 + h)*Ni + n)*64;
        o[l] = aa*inv; o[32+l] = ab*inv;
        __syncwarp();
    }
}

// ---------------- mix agg branches through M0/M1 ----------------
__global__ __launch_bounds__(128)
void combine_sg(const float* __restrict__ sx0, const float* __restrict__ sx1,
                const float* __restrict__ M0, const float* __restrict__ M1,
                float* __restrict__ sg)
{
    const int n = blockIdx.x, t = blockIdx.y, b = blockIdx.z;
    const int j = threadIdx.x, h = j>>6, d = j&63;
    const size_t bt = (size_t)b*Tt + t;
    float acc = 0.f;
    const float* s0 = sx0 + (bt*2+h)*(32*64) + d;
    #pragma unroll 4
    for (int m=0; m<32; m++) acc += M0[m*NN+n] * s0[m*64];
    const float* s1 = sx1 + (bt*2+h)*(64*64) + d;
    #pragma unroll 4
    for (int m=0; m<64; m++) acc += M1[m*NN+n] * s1[m*64];
    sg[(bt*NN+n)*128 + j] = acc;
}

// ---------------- temporal attention (t_x + tgx fused) ----------------
__global__ __launch_bounds__(128)
void temporal_kernel(const float* __restrict__ P, const float* __restrict__ q_agg,
                     float* __restrict__ st, float* __restrict__ tgx)
{
    extern __shared__ float sm[];
    const int n = blockIdx.x, b = blockIdx.y;
    const int wid = threadIdx.x >> 5, l = threadIdx.x & 31;
    const int w = wid & 1;        // head
    const int half = wid >> 1;    // query-range half
    float* base = sm + w*6240;
    float* kts = base;                 // 24 x 65
    float* vts = base + 1560;          // 24 x 64
    float* kgs = base + 3096;          // 24 x 65
    float* vgs = base + 4656;          // 24 x 64
    float* qp  = sm + 2*6240 + wid*96;
    float* qsh = qp;
    float* psh = qp + 64;
    for (int i = half*768 + l; i < half*768 + 768; i += 32){
        int t = i>>6, d = i&63;
        const float* row = P + (((size_t)b*Tt+t)*NN + n)*1408 + w*64;
        kts[t*65+d] = row[896+d];
        vts[t*64+d] = row[1024+d];
        kgs[t*65+d] = row[1152+d];
        vgs[t*64+d] = row[1280+d];
    }
    __syncthreads();
    for (int tq = half*12; tq < half*12 + 12; tq++){
        const float* qrow = P + (((size_t)b*Tt+tq)*NN + n)*1408 + w*64 + 768;
        qsh[l] = qrow[l]; qsh[32+l] = qrow[32+l];
        __syncwarp();
        float s = -1e30f;
        if (l < Tt){
            const float* kr = kts + l*65;
            float ts = 0.f;
            #pragma unroll
            for (int d=0; d<64; d++) ts += qsh[d]*kr[d];
            s = ts*0.125f;
        }
        float mx = warpMax(s);
        float e = (l < Tt) ? __expf(s-mx) : 0.f;
        float sum = warpSum(e);
        psh[l] = e;
        __syncwarp();
        float aa = 0.f, ab = 0.f;
        #pragma unroll
        for (int ss=0; ss<Tt; ss++){
            float p = psh[ss];
            aa += p*vts[ss*64+l]; ab += p*vts[ss*64+32+l];
        }
        float inv = 1.f/sum;
        float* o = st + (((size_t)b*Tt+tq)*NN + n)*640 + 384 + w*64;
        o[l] = aa*inv; o[32+l] = ab*inv;
        __syncwarp();
    }
    for (int sg_ = half*6; sg_ < half*6 + 6; sg_++){
        const float* qrow = q_agg + ((size_t)n*12 + sg_)*128 + w*64;
        qsh[l] = qrow[l]; qsh[32+l] = qrow[32+l];
        __syncwarp();
        float s = -1e30f;
        if (l < Tt){
            const float* kr = kgs + l*65;
            float ts = 0.f;
            #pragma unroll
            for (int d=0; d<64; d++) ts += qsh[d]*kr[d];
            s = ts*0.125f;
        }
        float mx = warpMax(s);
        float e = (l < Tt) ? __expf(s-mx) : 0.f;
        float sum = warpSum(e);
        psh[l] = e;
        __syncwarp();
        float aa = 0.f, ab = 0.f;
        #pragma unroll
        for (int ss=0; ss<Tt; ss++){
            float p = psh[ss];
            aa += p*vgs[ss*64+l]; ab += p*vgs[ss*64+32+l];
        }
        float inv = 1.f/sum;
        float* o = tgx + (((size_t)b*NN+n)*12 + sg_)*128 + w*64;
        o[l] = aa*inv; o[32+l] = ab*inv;
        __syncwarp();
    }
}

// ---------------- tg: mix tgx through tmp_map ----------------
__global__ __launch_bounds__(128)
void tg_scatter(const float* __restrict__ tmp_map, const float* __restrict__ tgx,
                float* __restrict__ st)
{
    const int n = blockIdx.x, t = blockIdx.y, b = blockIdx.z;
    const int j = threadIdx.x;
    const float* tm = tmp_map + (((size_t)b*NN + n)*Tt + t)*12;
    const float* g  = tgx + ((size_t)b*NN + n)*12*128 + j;
    float acc = 0.f;
    #pragma unroll
    for (int ss=0; ss<12; ss++) acc += tm[ss]*g[ss*128];
    st[(((size_t)b*Tt+t)*NN + n)*640 + 512 + j] = acc;
}

// ---------------- host ----------------
static inline void split_launch(const float* src, __nv_bfloat16* hi, __nv_bfloat16* lo,
                                int n, cudaStream_t s){
    split_bf16<<<(n/4 + 255)/256, 256, 0, s>>>(src, hi, lo, n);
}

extern "C" void kernel_launch(void* const* d_in, const int* in_sizes, int n_in,
                              void* d_out, int out_size)
{
    (void)in_sizes; (void)n_in; (void)out_size;
    const float* x       = (const float*)d_in[0];
    const float* agg_x0  = (const float*)d_in[1];
    const float* agg_x1  = (const float*)d_in[2];
    const float* tmp_map = (const float*)d_in[3];

    float *P, *P0, *P1, *Wcat, *Wcat0, *Wcat1, *sx0, *sx1, *sg, *tgx, *st;
    cudaGetSymbolAddress((void**)&P,     g_P);
    cudaGetSymbolAddress((void**)&P0,    g_P0);
    cudaGetSymbolAddress((void**)&P1,    g_P1);
    cudaGetSymbolAddress((void**)&Wcat,  g_Wcat);
    cudaGetSymbolAddress((void**)&Wcat0, g_Wcat0);
    cudaGetSymbolAddress((void**)&Wcat1, g_Wcat1);
    cudaGetSymbolAddress((void**)&sx0,   g_sx0);
    cudaGetSymbolAddress((void**)&sx1,   g_sx1);
    cudaGetSymbolAddress((void**)&sg,    g_sg);
    cudaGetSymbolAddress((void**)&tgx,   g_tgx);
    cudaGetSymbolAddress((void**)&st,    g_st);

    __nv_bfloat16 *xh,*xl,*a0h,*a0l,*a1h,*a1l,*Wh,*Wl,*W0h,*W0l,*W1h,*W1l;
    __nv_bfloat16 *sgh,*sgl,*Wah,*Wal,*sth,*stl,*Woh,*Wol;
    cudaGetSymbolAddress((void**)&xh,  g_xh);  cudaGetSymbolAddress((void**)&xl,  g_xl);
    cudaGetSymbolAddress((void**)&a0h, g_a0h); cudaGetSymbolAddress((void**)&a0l, g_a0l);
    cudaGetSymbolAddress((void**)&a1h, g_a1h); cudaGetSymbolAddress((void**)&a1l, g_a1l);
    cudaGetSymbolAddress((void**)&Wh,  g_Wh);  cudaGetSymbolAddress((void**)&Wl,  g_Wl);
    cudaGetSymbolAddress((void**)&W0h, g_W0h); cudaGetSymbolAddress((void**)&W0l, g_W0l);
    cudaGetSymbolAddress((void**)&W1h, g_W1h); cudaGetSymbolAddress((void**)&W1l, g_W1l);
    cudaGetSymbolAddress((void**)&sgh, g_sgh); cudaGetSymbolAddress((void**)&sgl, g_sgl);
    cudaGetSymbolAddress((void**)&Wah, g_Wah); cudaGetSymbolAddress((void**)&Wal, g_Wal);
    cudaGetSymbolAddress((void**)&sth, g_sth); cudaGetSymbolAddress((void**)&stl, g_stl);
    cudaGetSymbolAddress((void**)&Woh, g_Woh); cudaGetSymbolAddress((void**)&Wol, g_Wol);

    cudaFuncSetAttribute(gemm_tc,         cudaFuncAttributeMaxDynamicSharedMemorySize, 55296);
    cudaFuncSetAttribute(spatial_kernel,  cudaFuncAttributeMaxDynamicSharedMemorySize, 180960);
    cudaFuncSetAttribute(temporal_kernel, cudaFuncAttributeMaxDynamicSharedMemorySize, 51456);

    cudaStream_t s = 0;
    const size_t W512 = (size_t)512 * sizeof(float);
    // concat x-projection weights: [Wq_s, Wk_s, Wv_s, Wq_t, Wk_t, Wv_t, Wk_tg, Wv_tg]
    cudaMemcpyAsync(Wcat + (size_t)   0*512, d_in[4],  256*W512, cudaMemcpyDeviceToDevice, s);
    cudaMemcpyAsync(Wcat + (size_t) 256*512, d_in[5],  256*W512, cudaMemcpyDeviceToDevice, s);
    cudaMemcpyAsync(Wcat + (size_t) 512*512, d_in[6],  256*W512, cudaMemcpyDeviceToDevice, s);
    cudaMemcpyAsync(Wcat + (size_t) 768*512, d_in[23], 128*W512, cudaMemcpyDeviceToDevice, s);
    cudaMemcpyAsync(Wcat + (size_t) 896*512, d_in[24], 128*W512, cudaMemcpyDeviceToDevice, s);
    cudaMemcpyAsync(Wcat + (size_t)1024*512, d_in[25], 128*W512, cudaMemcpyDeviceToDevice, s);
    cudaMemcpyAsync(Wcat + (size_t)1152*512, d_in[27], 128*W512, cudaMemcpyDeviceToDevice, s);
    cudaMemcpyAsync(Wcat + (size_t)1280*512, d_in[28], 128*W512, cudaMemcpyDeviceToDevice, s);
    // agg weights
    cudaMemcpyAsync(Wcat0 + (size_t)  0*512, d_in[13], 128*W512, cudaMemcpyDeviceToDevice, s);
    cudaMemcpyAsync(Wcat0 + (size_t)128*512, d_in[14], 128*W512, cudaMemcpyDeviceToDevice, s);
    cudaMemcpyAsync(Wcat0 + (size_t)256*512, d_in[15], 128*W512, cudaMemcpyDeviceToDevice, s);
    cudaMemcpyAsync(Wcat1 + (size_t)  0*512, d_in[16], 128*W512, cudaMemcpyDeviceToDevice, s);
    cudaMemcpyAsync(Wcat1 + (size_t)128*512, d_in[17], 128*W512, cudaMemcpyDeviceToDevice, s);
    cudaMemcpyAsync(Wcat1 + (size_t)256*512, d_in[18], 128*W512, cudaMemcpyDeviceToDevice, s);

    lam_kernel<<<1,32,0,s>>>((const float*)d_in[7], (const float*)d_in[8],
                             (const float*)d_in[9], (const float*)d_in[10]);

    // splits for projection inputs/weights
    split_launch(x,       xh,  xl,  50496*512, s);
    split_launch(agg_x0,  a0h, a0l, 6144*512, s);
    split_launch(agg_x1,  a1h, a1l, 12288*512, s);
    split_launch(Wcat,    Wh,  Wl,  1408*512, s);
    split_launch(Wcat0,   W0h, W0l, 384*512, s);
    split_launch(Wcat1,   W1h, W1l, 384*512, s);
    split_launch((const float*)d_in[21], Wah, Wal, 128*128, s);
    split_launch((const float*)d_in[29], Woh, Wol, 512*640, s);

    // projections
    gemm_tc<<<dim3(11, 789), 256, 55296, s>>>(xh, xl, Wh, Wl, P,  nullptr, 50496, 1408, 512, 1408, 0);
    gemm_tc<<<dim3(3,   96), 256, 55296, s>>>(a0h, a0l, W0h, W0l, P0, nullptr, 6144, 384, 512, 384, 0);
    gemm_tc<<<dim3(3,  192), 256, 55296, s>>>(a1h, a1l, W1h, W1l, P1, nullptr, 12288, 384, 512, 384, 0);

    // branch 1: spatial diff attention -> st[:,0:256]
    spatial_kernel<<<dim3(4, Tt, Bb), 512, 180960, s>>>(P, st,
        (const float*)d_in[11], (const float*)d_in[12]);

    // branch 2: agg attention + mix + Wagg -> st[:,256:384]
    agg_attn<<<dim3(2, Tt, Bb), 256, 0, s>>>(P0, sx0, 32);
    agg_attn<<<dim3(2, Tt, Bb), 256, 0, s>>>(P1, sx1, 64);
    combine_sg<<<dim3(NN, Tt, Bb), 128, 0, s>>>(sx0, sx1,
        (const float*)d_in[19], (const float*)d_in[20], sg);
    split_launch(sg, sgh, sgl, 50496*128, s);
    gemm_tc<<<dim3(1, 789), 256, 55296, s>>>(sgh, sgl, Wah, Wal, st,
        (const float*)d_in[22], 50496, 128, 128, 640, 256);

    // branches 3+4: temporal attention -> st[:,384:512], tgx; then tg -> st[:,512:640]
    temporal_kernel<<<dim3(NN, Bb), 128, 51456, s>>>(P, (const float*)d_in[26], st, tgx);
    tg_scatter<<<dim3(NN, Tt, Bb), 128, 0, s>>>(tmp_map, tgx, st);

    // output projection
    split_launch(st, sth, stl, 50496*640, s);
    gemm_tc<<<dim3(4, 789), 256, 55296, s>>>(sth, stl, Woh, Wol, (float*)d_out,
        (const float*)d_in[30], 50496, 512, 640, 512, 0);
}